// round 2
// baseline (speedup 1.0000x reference)
#include <cuda_runtime.h>

// Fan-beam CT forward projector, gather formulation.
// Geometry constants (fixed by the problem's init_kwargs).
constexpr int   R_      = 384;
constexpr int   C_      = 384;
constexpr int   NCOLS_  = 768;
constexpr int   V_      = 256;
constexpr float DR_     = 1.0f;
constexpr float DC_     = 1.0f;
constexpr float DSPACE_ = 1.5f;

struct ViewGeom {
    float sx, sy, ux, uy, nx, ny;
    float vzx, vzy, rowx, rowy, colx, coly;
    float K, src_d, su, A;
};

__global__ __launch_bounds__(256)
void fanbeam_fp_kernel(const float* __restrict__ img,
                       const float* __restrict__ src_g,    // (V,1,2)
                       const float* __restrict__ detc_g,   // (V,1,2)
                       const float* __restrict__ u_g,      // (V,1,2)
                       const float* __restrict__ center_g, // (2)
                       const float* __restrict__ cdir_g,   // (2)
                       float* __restrict__ sino)           // (V,NCOLS)
{
    const int v = blockIdx.y;
    const int i = blockIdx.x * blockDim.x + threadIdx.x;

    __shared__ ViewGeom g;
    if (threadIdx.x == 0) {
        const float sx  = src_g [2*v+0], sy  = src_g [2*v+1];
        const float dcx = detc_g[2*v+0], dcy = detc_g[2*v+1];
        const float ux  = u_g  [2*v+0], uy  = u_g  [2*v+1];
        const float nx  = -uy,          ny  = ux;            // detector normal
        const float cx  = center_g[0],  cy  = center_g[1];
        const float colx = cdir_g[0],   coly = cdir_g[1];
        const float rowx = -coly,       rowy = colx;

        g.sx = sx; g.sy = sy; g.ux = ux; g.uy = uy; g.nx = nx; g.ny = ny;
        g.rowx = rowx; g.rowy = rowy; g.colx = colx; g.coly = coly;

        g.vzx = cx - 0.5f*(R_-1)*DR_*rowx - 0.5f*(C_-1)*DC_*colx;
        g.vzy = cy - 0.5f*(R_-1)*DR_*rowy - 0.5f*(C_-1)*DC_*coly;

        const float ref_d = dcx*nx + dcy*ny;
        g.src_d = sx*nx + sy*ny;
        g.K     = ref_d - g.src_d;                 // t numerator
        g.su    = sx*ux + sy*uy;
        const float h   = 0.5f*(NCOLS_-1)*DSPACE_;
        const float dzx = dcx - h*ux, dzy = dcy - h*uy;   // detector_zero
        const float zero_u = dzx*ux + dzy*uy;
        g.A     = g.su - zero_u;                   // proj offset
    }
    __syncthreads();
    if (i >= NCOLS_) return;

    const float sx = g.sx, sy = g.sy, ux = g.ux, uy = g.uy;
    const float nx = g.nx, ny = g.ny;
    const float rowx = g.rowx, rowy = g.rowy, colx = g.colx, coly = g.coly;
    const float vzx = g.vzx, vzy = g.vzy;
    const float K = g.K, src_d = g.src_d, su = g.su, A = g.A;

    // central ray of this bin -> choose driving axis
    // bin position = detector_zero + i*DSPACE*u; dir = bin - src
    const float h   = 0.5f*(NCOLS_-1)*DSPACE_;
    const float bgx = (vzx*0.0f); (void)bgx; // keep compiler calm
    const float bx  = ( - h*ux + (float)i*DSPACE_*ux);   // relative offsets cancel in comparison
    // Recompute bin pos exactly from detector geometry stored in g:
    // det_zero = det_c - h*u. We didn't store det_c, but dir only feeds the
    // axis choice (a comparison), so reconstruct via A/su relation is overkill;
    // store det_c components through nx/ny: det_c = ref_d*n + (su - A... ) --
    // simpler: axis choice from ray direction ≈ (det_c - src) + (i*DS - h)*u.
    // ref_d*n is the normal component of det_c; its tangential component is
    // (det_c . u) * u = (zero_u + h) * u = (su - A + h) * u.
    const float ref_d = K + src_d;
    const float dcux  = (su - A + h);                      // det_c . u
    const float dirx = (ref_d*nx + dcux*ux) - sx + ((float)i*DSPACE_ - h)*ux;
    const float diry = (ref_d*ny + dcux*uy) - sy + ((float)i*DSPACE_ - h)*uy;
    (void)bx;
    const float dc_comp = dirx*colx + diry*coly;   // advance along image-col axis
    const float dr_comp = dirx*rowx + diry*rowy;   // advance along image-row axis

    // wedge boundaries in "e" space: e(gamma) = gamma*DSPACE - A
    const float em = (float)(i-1)*DSPACE_ - A;
    const float ep = (float)(i+1)*DSPACE_ - A;

    float acc = 0.0f;
    const float inv_ds = 1.0f / DSPACE_;

    if (fabsf(dc_comp) >= fabsf(dr_comp)) {
        // ---- drive over image columns c, solve row range r ----
        const float gn = DR_*(rowx*nx + rowy*ny);   // d(P.n)/dr
        const float gu = DR_*(rowx*ux + rowy*uy);   // d(P.u)/dr
        #pragma unroll 2
        for (int c = 0; c < C_; ++c) {
            const float p0x = vzx + (float)c*DC_*colx;
            const float p0y = vzy + (float)c*DC_*coly;
            const float bn  = p0x*nx + p0y*ny - src_d;   // P.n - src_d at r=0
            const float bu  = p0x*ux + p0y*uy - su;      // P.u - su   at r=0
            // solve col(P)=i-1 / i+1 for r (linear in r)
            const float ra = (em*bn - K*bu) / (K*gu - em*gn);
            const float rb = (ep*bn - K*bu) / (K*gu - ep*gn);
            float lo = fminf(ra, rb), hi = fmaxf(ra, rb);
            if (!(hi >= lo)) { lo = 0.0f; hi = (float)(R_-1); }  // NaN fallback
            if (hi < 0.0f || lo > (float)(R_-1)) continue;
            const int r0 = (int)floorf(fmaxf(lo, 0.0f));
            const int r1 = (int)ceilf (fminf(hi, (float)(R_-1)));
            for (int r = r0; r <= r1; ++r) {
                const float den = bn + (float)r*gn;     // P.n - src_d
                const float pu  = bu + (float)r*gu;     // P.u - su
                const float t   = K / den;
                const float col = (A + t*pu) * inv_ds;
                const float w   = 1.0f - fabsf(col - (float)i);
                if (w > 0.0f && t > 0.0f)
                    acc += w * img[r*C_ + c];
            }
        }
    } else {
        // ---- drive over image rows r, solve column range c ----
        const float gn = DC_*(colx*nx + coly*ny);   // d(P.n)/dc
        const float gu = DC_*(colx*ux + coly*uy);   // d(P.u)/dc
        #pragma unroll 2
        for (int r = 0; r < R_; ++r) {
            const float p0x = vzx + (float)r*DR_*rowx;
            const float p0y = vzy + (float)r*DR_*rowy;
            const float bn  = p0x*nx + p0y*ny - src_d;
            const float bu  = p0x*ux + p0y*uy - su;
            const float ca_ = (em*bn - K*bu) / (K*gu - em*gn);
            const float cb_ = (ep*bn - K*bu) / (K*gu - ep*gn);
            float lo = fminf(ca_, cb_), hi = fmaxf(ca_, cb_);
            if (!(hi >= lo)) { lo = 0.0f; hi = (float)(C_-1); }
            if (hi < 0.0f || lo > (float)(C_-1)) continue;
            const int c0 = (int)floorf(fmaxf(lo, 0.0f));
            const int c1 = (int)ceilf (fminf(hi, (float)(C_-1)));
            const float* rowp = img + r*C_;
            for (int c = c0; c <= c1; ++c) {
                const float den = bn + (float)c*gn;
                const float pu  = bu + (float)c*gu;
                const float t   = K / den;
                const float col = (A + t*pu) * inv_ds;
                const float w   = 1.0f - fabsf(col - (float)i);
                if (w > 0.0f && t > 0.0f)
                    acc += w * rowp[c];
            }
        }
    }

    sino[v*NCOLS_ + i] = acc;
}

extern "C" void kernel_launch(void* const* d_in, const int* in_sizes, int n_in,
                              void* d_out, int out_size)
{
    const float* img    = (const float*)d_in[0]; // (384,384)
    const float* src    = (const float*)d_in[1]; // (256,1,2)
    const float* detc   = (const float*)d_in[2]; // (256,1,2)
    const float* u      = (const float*)d_in[3]; // (256,1,2)
    const float* center = (const float*)d_in[4]; // (2)
    const float* cdir   = (const float*)d_in[5]; // (2)
    float* sino = (float*)d_out;                 // (256,1,1,768)

    dim3 grid(NCOLS_ / 256, V_);
    dim3 block(256);
    fanbeam_fp_kernel<<<grid, block>>>(img, src, detc, u, center, cdir, sino);
}

// round 3
// speedup vs baseline: 2.1873x; 2.1873x over previous
#include <cuda_runtime.h>

// Fan-beam CT forward projector — gather with precomputed linear wedge bounds.
constexpr int   R_      = 384;
constexpr int   C_      = 384;
constexpr int   NCOLS_  = 768;
constexpr int   V_      = 256;
constexpr float DR_     = 1.0f;
constexpr float DC_     = 1.0f;
constexpr float DSPACE_ = 1.5f;

struct VG {
    float nx, ny, ux, uy;
    float rowx, rowy, colx, coly;
    float K, A, su, src_d;
    float bn0, dnr, dnc;      // den(r,c)  = bn0 + r*dnr + c*dnc   (P.n - src_d)
    float bu0, dur, duc;      // pu(r,c)   = bu0 + r*dur + c*duc   (P.u - su)
    float dzx, dzy, sx, sy;   // detector zero pos, source pos
};

__global__ __launch_bounds__(128)
void fanbeam_fp_kernel(const float* __restrict__ img,
                       const float* __restrict__ src_g,
                       const float* __restrict__ detc_g,
                       const float* __restrict__ u_g,
                       const float* __restrict__ center_g,
                       const float* __restrict__ cdir_g,
                       float* __restrict__ sino)
{
    const int v = blockIdx.y;
    const int i = blockIdx.x * blockDim.x + threadIdx.x;

    __shared__ VG g;
    if (threadIdx.x == 0) {
        const float sx  = src_g [2*v+0], sy  = src_g [2*v+1];
        const float dcx = detc_g[2*v+0], dcy = detc_g[2*v+1];
        const float ux  = u_g  [2*v+0], uy  = u_g  [2*v+1];
        const float nx  = -uy,          ny  = ux;
        const float cx  = center_g[0],  cy  = center_g[1];
        const float colx = cdir_g[0],   coly = cdir_g[1];
        const float rowx = -coly,       rowy = colx;

        const float vzx = cx - 0.5f*(R_-1)*DR_*rowx - 0.5f*(C_-1)*DC_*colx;
        const float vzy = cy - 0.5f*(R_-1)*DR_*rowy - 0.5f*(C_-1)*DC_*coly;

        const float src_d = sx*nx + sy*ny;
        const float su    = sx*ux + sy*uy;
        const float K     = (dcx*nx + dcy*ny) - src_d;
        const float h     = 0.5f*(NCOLS_-1)*DSPACE_;
        const float dzx   = dcx - h*ux, dzy = dcy - h*uy;
        const float A     = su - (dzx*ux + dzy*uy);

        g.nx = nx; g.ny = ny; g.ux = ux; g.uy = uy;
        g.rowx = rowx; g.rowy = rowy; g.colx = colx; g.coly = coly;
        g.K = K; g.A = A; g.su = su; g.src_d = src_d;
        g.bn0 = vzx*nx + vzy*ny - src_d;
        g.dnr = DR_*(rowx*nx + rowy*ny);
        g.dnc = DC_*(colx*nx + coly*ny);
        g.bu0 = vzx*ux + vzy*uy - su;
        g.dur = DR_*(rowx*ux + rowy*uy);
        g.duc = DC_*(colx*ux + coly*uy);
        g.dzx = dzx; g.dzy = dzy; g.sx = sx; g.sy = sy;
    }
    __syncthreads();

    const float K = g.K, A = g.A;
    const float bn0 = g.bn0, dnr = g.dnr, dnc = g.dnc;
    const float bu0 = g.bu0, dur = g.dur, duc = g.duc;

    // sign of den across the image (source outside image => constant sign)
    const float den_c = bn0 + 0.5f*(R_-1)*dnr + 0.5f*(C_-1)*dnc;
    const float sig   = (den_c > 0.0f) ? 1.0f : -1.0f;
    const bool  tok   = (sig * K) > 0.0f;   // t>0 holds wherever B'>0

    // Q = (A - i*DS)*den + K*pu ; B = DS*den ; primed = *sig
    const float E  = A - (float)i * DSPACE_;
    const float q0 = sig * (E*bn0 + K*bu0);
    const float qr = sig * (E*dnr + K*dur);
    const float qc = sig * (E*dnc + K*duc);
    const float b0 = sig * DSPACE_ * bn0;
    const float br = sig * DSPACE_ * dnr;
    const float bc = sig * DSPACE_ * dnc;

    // driving-axis choice from the bin's central ray direction
    const float bxp = g.dzx + (float)i*DSPACE_*g.ux - g.sx;
    const float byp = g.dzy + (float)i*DSPACE_*g.uy - g.sy;
    const float dc_comp = bxp*g.colx + byp*g.coly;
    const float dr_comp = bxp*g.rowx + byp*g.rowy;

    float acc = 0.0f;

    if (tok) {
        if (fabsf(dc_comp) >= fabsf(dr_comp)) {
            // drive over c; wedge bounds in r are linear in c
            const float gm = qr + br, gp = qr - br;
            const float invm = 1.0f/gm, invp = 1.0f/gp;
            const float am = -(q0 + b0)*invm, bm = -(qc + bc)*invm;
            const float ap = -(q0 - b0)*invp, bp2 = -(qc - bc)*invp;
            float cf = 0.0f;
            for (int c = 0; c < C_; ++c, cf += 1.0f) {
                const float r1 = fmaf(cf, bm, am);
                const float r2 = fmaf(cf, bp2, ap);
                float lo = fmaxf(fminf(r1, r2) - 0.01f, 0.0f);
                float hi = fminf(fmaxf(r1, r2) + 0.01f, (float)(R_-1));
                if (!(hi >= lo)) continue;
                const int ir0 = __float2int_ru(lo);
                const int ir1 = __float2int_rd(hi);
                const float Qb = fmaf(cf, qc, q0);
                const float Bb = fmaf(cf, bc, b0);
                float rf = (float)ir0;
                for (int r = ir0; r <= ir1; ++r, rf += 1.0f) {
                    const float Qp = fmaf(rf, qr, Qb);
                    const float Bp = fmaf(rf, br, Bb);
                    const float w  = 1.0f - __fdividef(fabsf(Qp), Bp);
                    if (w > 0.0f && Bp > 0.0f)
                        acc = fmaf(w, __ldg(img + r*C_ + c), acc);
                }
            }
        } else {
            // drive over r; wedge bounds in c are linear in r
            const float gm = qc + bc, gp = qc - bc;
            const float invm = 1.0f/gm, invp = 1.0f/gp;
            const float am = -(q0 + b0)*invm, bm = -(qr + br)*invm;
            const float ap = -(q0 - b0)*invp, bp2 = -(qr - br)*invp;
            float rfd = 0.0f;
            for (int r = 0; r < R_; ++r, rfd += 1.0f) {
                const float c1 = fmaf(rfd, bm, am);
                const float c2 = fmaf(rfd, bp2, ap);
                float lo = fmaxf(fminf(c1, c2) - 0.01f, 0.0f);
                float hi = fminf(fmaxf(c1, c2) + 0.01f, (float)(C_-1));
                if (!(hi >= lo)) continue;
                const int ic0 = __float2int_ru(lo);
                const int ic1 = __float2int_rd(hi);
                const float Qb = fmaf(rfd, qr, q0);
                const float Bb = fmaf(rfd, br, b0);
                const float* rowp = img + r*C_;
                float cf = (float)ic0;
                for (int c = ic0; c <= ic1; ++c, cf += 1.0f) {
                    const float Qp = fmaf(cf, qc, Qb);
                    const float Bp = fmaf(cf, bc, Bb);
                    const float w  = 1.0f - __fdividef(fabsf(Qp), Bp);
                    if (w > 0.0f && Bp > 0.0f)
                        acc = fmaf(w, __ldg(rowp + c), acc);
                }
            }
        }
    }

    sino[v*NCOLS_ + i] = acc;
}

extern "C" void kernel_launch(void* const* d_in, const int* in_sizes, int n_in,
                              void* d_out, int out_size)
{
    const float* img    = (const float*)d_in[0];
    const float* src    = (const float*)d_in[1];
    const float* detc   = (const float*)d_in[2];
    const float* u      = (const float*)d_in[3];
    const float* center = (const float*)d_in[4];
    const float* cdir   = (const float*)d_in[5];
    float* sino = (float*)d_out;

    dim3 grid(NCOLS_ / 128, V_);
    dim3 block(128);
    fanbeam_fp_kernel<<<grid, block>>>(img, src, detc, u, center, cdir, sino);
}

// round 4
// speedup vs baseline: 4.2728x; 1.9535x over previous
#include <cuda_runtime.h>

// Fan-beam CT forward projector — warp-cooperative gather.
// One warp per (view, detector bin); 32 lanes split the 384 driving steps.
constexpr int   R_      = 384;
constexpr int   C_      = 384;
constexpr int   NCOLS_  = 768;
constexpr int   V_      = 256;
constexpr float DR_     = 1.0f;
constexpr float DC_     = 1.0f;
constexpr float DSPACE_ = 1.5f;

constexpr int WARPS_PER_BLOCK = 4;
constexpr int STEPS_PER_LANE  = 384 / 32;   // 12

struct VG {
    float K, A;
    float bn0, dnr, dnc;      // den(r,c) = bn0 + r*dnr + c*dnc   (P.n - src_d)
    float bu0, dur, duc;      // pu(r,c)  = bu0 + r*dur + c*duc   (P.u - su)
    float dzx, dzy, sx, sy;   // detector zero, source
    float ux, uy, rowx, rowy, colx, coly;
};

__global__ __launch_bounds__(32 * WARPS_PER_BLOCK)
void fanbeam_fp_kernel(const float* __restrict__ img,
                       const float* __restrict__ src_g,
                       const float* __restrict__ detc_g,
                       const float* __restrict__ u_g,
                       const float* __restrict__ center_g,
                       const float* __restrict__ cdir_g,
                       float* __restrict__ sino)
{
    const int v    = blockIdx.y;
    const int warp = threadIdx.x >> 5;
    const int lane = threadIdx.x & 31;
    const int i    = blockIdx.x * WARPS_PER_BLOCK + warp;   // detector bin

    __shared__ VG g;
    if (threadIdx.x == 0) {
        const float sx  = src_g [2*v+0], sy  = src_g [2*v+1];
        const float dcx = detc_g[2*v+0], dcy = detc_g[2*v+1];
        const float ux  = u_g  [2*v+0], uy  = u_g  [2*v+1];
        const float nx  = -uy,          ny  = ux;
        const float cx  = center_g[0],  cy  = center_g[1];
        const float colx = cdir_g[0],   coly = cdir_g[1];
        const float rowx = -coly,       rowy = colx;

        const float vzx = cx - 0.5f*(R_-1)*DR_*rowx - 0.5f*(C_-1)*DC_*colx;
        const float vzy = cy - 0.5f*(R_-1)*DR_*rowy - 0.5f*(C_-1)*DC_*coly;

        const float src_d = sx*nx + sy*ny;
        const float su    = sx*ux + sy*uy;
        const float K     = (dcx*nx + dcy*ny) - src_d;
        const float h     = 0.5f*(NCOLS_-1)*DSPACE_;
        const float dzx   = dcx - h*ux, dzy = dcy - h*uy;
        const float A     = su - (dzx*ux + dzy*uy);

        g.K = K; g.A = A;
        g.bn0 = vzx*nx + vzy*ny - src_d;
        g.dnr = DR_*(rowx*nx + rowy*ny);
        g.dnc = DC_*(colx*nx + coly*ny);
        g.bu0 = vzx*ux + vzy*uy - su;
        g.dur = DR_*(rowx*ux + rowy*uy);
        g.duc = DC_*(colx*ux + coly*uy);
        g.dzx = dzx; g.dzy = dzy; g.sx = sx; g.sy = sy;
        g.ux = ux; g.uy = uy;
        g.rowx = rowx; g.rowy = rowy; g.colx = colx; g.coly = coly;
    }
    __syncthreads();

    const float K = g.K, A = g.A;
    const float bn0 = g.bn0, dnr = g.dnr, dnc = g.dnc;
    const float bu0 = g.bu0, dur = g.dur, duc = g.duc;

    // sign of den across the image (source outside image => constant sign)
    const float den_c = bn0 + 0.5f*(R_-1)*dnr + 0.5f*(C_-1)*dnc;
    const float sig   = (den_c > 0.0f) ? 1.0f : -1.0f;
    const bool  tok   = (sig * K) > 0.0f;

    // Q = (A - i*DS)*den + K*pu ; B = DS*den ; primed = *sig
    const float E  = A - (float)i * DSPACE_;
    const float q0 = sig * (E*bn0 + K*bu0);
    const float qr = sig * (E*dnr + K*dur);
    const float qc = sig * (E*dnc + K*duc);
    const float b0 = sig * DSPACE_ * bn0;
    const float br = sig * DSPACE_ * dnr;
    const float bc = sig * DSPACE_ * dnc;

    // driving-axis choice from bin's central ray (warp-uniform)
    const float bxp = g.dzx + (float)i*DSPACE_*g.ux - g.sx;
    const float byp = g.dzy + (float)i*DSPACE_*g.uy - g.sy;
    const float dc_comp = bxp*g.colx + byp*g.coly;
    const float dr_comp = bxp*g.rowx + byp*g.rowy;

    float acc = 0.0f;

    if (tok) {
        if (fabsf(dc_comp) >= fabsf(dr_comp)) {
            // drive over c (lanes take c = lane + 32k); solve r range
            const float gm = qr + br, gp = qr - br;
            const float invm = 1.0f/gm, invp = 1.0f/gp;
            const float am = -(q0 + b0)*invm, bm = -(qc + bc)*invm;
            const float ap = -(q0 - b0)*invp, bp2 = -(qc - bc)*invp;
            float cf = (float)lane;
            int   ci = lane;
            #pragma unroll 2
            for (int j = 0; j < STEPS_PER_LANE; ++j, cf += 32.0f, ci += 32) {
                const float r1 = fmaf(cf, bm, am);
                const float r2 = fmaf(cf, bp2, ap);
                const float lo = fmaxf(fminf(r1, r2) - 0.01f, 0.0f);
                const float hi = fminf(fmaxf(r1, r2) + 0.01f, (float)(R_-1));
                if (hi >= lo) {
                    const int ir0 = __float2int_ru(lo);
                    const int ir1 = __float2int_rd(hi);
                    const float Qb = fmaf(cf, qc, q0);
                    const float Bb = fmaf(cf, bc, b0);
                    float rf = (float)ir0;
                    for (int r = ir0; r <= ir1; ++r, rf += 1.0f) {
                        const float Qp = fmaf(rf, qr, Qb);
                        const float Bp = fmaf(rf, br, Bb);
                        const float w  = 1.0f - __fdividef(fabsf(Qp), Bp);
                        if (w > 0.0f && Bp > 0.0f)
                            acc = fmaf(w, __ldg(img + r*C_ + ci), acc);
                    }
                }
            }
        } else {
            // drive over r (lanes take r = lane + 32k); solve c range
            const float gm = qc + bc, gp = qc - bc;
            const float invm = 1.0f/gm, invp = 1.0f/gp;
            const float am = -(q0 + b0)*invm, bm = -(qr + br)*invm;
            const float ap = -(q0 - b0)*invp, bp2 = -(qr - br)*invp;
            float rfd = (float)lane;
            int   ri  = lane;
            #pragma unroll 2
            for (int j = 0; j < STEPS_PER_LANE; ++j, rfd += 32.0f, ri += 32) {
                const float c1 = fmaf(rfd, bm, am);
                const float c2 = fmaf(rfd, bp2, ap);
                const float lo = fmaxf(fminf(c1, c2) - 0.01f, 0.0f);
                const float hi = fminf(fmaxf(c1, c2) + 0.01f, (float)(C_-1));
                if (hi >= lo) {
                    const int ic0 = __float2int_ru(lo);
                    const int ic1 = __float2int_rd(hi);
                    const float Qb = fmaf(rfd, qr, q0);
                    const float Bb = fmaf(rfd, br, b0);
                    const float* rowp = img + ri*C_;
                    float cf = (float)ic0;
                    for (int c = ic0; c <= ic1; ++c, cf += 1.0f) {
                        const float Qp = fmaf(cf, qc, Qb);
                        const float Bp = fmaf(cf, bc, Bb);
                        const float w  = 1.0f - __fdividef(fabsf(Qp), Bp);
                        if (w > 0.0f && Bp > 0.0f)
                            acc = fmaf(w, __ldg(rowp + c), acc);
                    }
                }
            }
        }
    }

    // warp reduction
    #pragma unroll
    for (int off = 16; off > 0; off >>= 1)
        acc += __shfl_xor_sync(0xffffffffu, acc, off);

    if (lane == 0)
        sino[v*NCOLS_ + i] = acc;
}

extern "C" void kernel_launch(void* const* d_in, const int* in_sizes, int n_in,
                              void* d_out, int out_size)
{
    const float* img    = (const float*)d_in[0];
    const float* src    = (const float*)d_in[1];
    const float* detc   = (const float*)d_in[2];
    const float* u      = (const float*)d_in[3];
    const float* center = (const float*)d_in[4];
    const float* cdir   = (const float*)d_in[5];
    float* sino = (float*)d_out;

    dim3 grid(NCOLS_ / WARPS_PER_BLOCK, V_);
    dim3 block(32 * WARPS_PER_BLOCK);
    fanbeam_fp_kernel<<<grid, block>>>(img, src, detc, u, center, cdir, sino);
}

// round 5
// speedup vs baseline: 5.2862x; 1.2372x over previous
#include <cuda_runtime.h>

// Fan-beam CT forward projector — warp-cooperative gather, slim inner loop.
constexpr int   R_      = 384;
constexpr int   C_      = 384;
constexpr int   NCOLS_  = 768;
constexpr int   V_      = 256;
constexpr float DR_     = 1.0f;
constexpr float DC_     = 1.0f;
constexpr float DSPACE_ = 1.5f;

constexpr int WARPS_PER_BLOCK = 4;
constexpr int STEPS_PER_LANE  = 384 / 32;   // 12

struct VG {
    float K, A;
    float bn0, dnr, dnc;      // den(r,c) = bn0 + r*dnr + c*dnc
    float bu0, dur, duc;      // pu(r,c)  = bu0 + r*dur + c*duc
    float dzx, dzy, sx, sy;
    float ux, uy, rowx, rowy, colx, coly;
};

__global__ __launch_bounds__(32 * WARPS_PER_BLOCK)
void fanbeam_fp_kernel(const float* __restrict__ img,
                       const float* __restrict__ src_g,
                       const float* __restrict__ detc_g,
                       const float* __restrict__ u_g,
                       const float* __restrict__ center_g,
                       const float* __restrict__ cdir_g,
                       float* __restrict__ sino)
{
    const int v    = blockIdx.y;
    const int warp = threadIdx.x >> 5;
    const int lane = threadIdx.x & 31;
    const int i    = blockIdx.x * WARPS_PER_BLOCK + warp;

    __shared__ VG g;
    if (threadIdx.x == 0) {
        const float sx  = src_g [2*v+0], sy  = src_g [2*v+1];
        const float dcx = detc_g[2*v+0], dcy = detc_g[2*v+1];
        const float ux  = u_g  [2*v+0], uy  = u_g  [2*v+1];
        const float nx  = -uy,          ny  = ux;
        const float cx  = center_g[0],  cy  = center_g[1];
        const float colx = cdir_g[0],   coly = cdir_g[1];
        const float rowx = -coly,       rowy = colx;

        const float vzx = cx - 0.5f*(R_-1)*DR_*rowx - 0.5f*(C_-1)*DC_*colx;
        const float vzy = cy - 0.5f*(R_-1)*DR_*rowy - 0.5f*(C_-1)*DC_*coly;

        const float src_d = sx*nx + sy*ny;
        const float su    = sx*ux + sy*uy;
        const float K     = (dcx*nx + dcy*ny) - src_d;
        const float h     = 0.5f*(NCOLS_-1)*DSPACE_;
        const float dzx   = dcx - h*ux, dzy = dcy - h*uy;
        const float A     = su - (dzx*ux + dzy*uy);

        g.K = K; g.A = A;
        g.bn0 = vzx*nx + vzy*ny - src_d;
        g.dnr = DR_*(rowx*nx + rowy*ny);
        g.dnc = DC_*(colx*nx + coly*ny);
        g.bu0 = vzx*ux + vzy*uy - su;
        g.dur = DR_*(rowx*ux + rowy*uy);
        g.duc = DC_*(colx*ux + coly*uy);
        g.dzx = dzx; g.dzy = dzy; g.sx = sx; g.sy = sy;
        g.ux = ux; g.uy = uy;
        g.rowx = rowx; g.rowy = rowy; g.colx = colx; g.coly = coly;
    }
    __syncthreads();

    const float K = g.K, A = g.A;
    const float bn0 = g.bn0, dnr = g.dnr, dnc = g.dnc;
    const float bu0 = g.bu0, dur = g.dur, duc = g.duc;

    const float den_c = bn0 + 0.5f*(R_-1)*dnr + 0.5f*(C_-1)*dnc;
    const float sig   = (den_c > 0.0f) ? 1.0f : -1.0f;
    const bool  tok   = (sig * K) > 0.0f;

    const float E  = A - (float)i * DSPACE_;
    const float q0 = sig * (E*bn0 + K*bu0);
    const float qr = sig * (E*dnr + K*dur);
    const float qc = sig * (E*dnc + K*duc);
    const float b0 = sig * DSPACE_ * bn0;
    const float br = sig * DSPACE_ * dnr;
    const float bc = sig * DSPACE_ * dnc;

    const float bxp = g.dzx + (float)i*DSPACE_*g.ux - g.sx;
    const float byp = g.dzy + (float)i*DSPACE_*g.uy - g.sy;
    const float dc_comp = bxp*g.colx + byp*g.coly;
    const float dr_comp = bxp*g.rowx + byp*g.rowy;

    float acc = 0.0f;

    if (tok) {
        if (fabsf(dc_comp) >= fabsf(dr_comp)) {
            // ---- drive over c (lanes take c = lane + 32k); solve r range ----
            const float gm = qr + br, gp = qr - br;
            const float invm = 1.0f/gm, invp = 1.0f/gp;
            float am = -(q0 + b0)*invm, bm = -(qc + bc)*invm;
            float ap = -(q0 - b0)*invp, bp2 = -(qc - bc)*invp;
            // boundary ordering is constant across the image (crossing at src)
            float alo, blo, ahi, bhi;
            if (fmaf(191.5f, bm, am) <= fmaf(191.5f, bp2, ap)) {
                alo = am; blo = bm; ahi = ap; bhi = bp2;
            } else {
                alo = ap; blo = bp2; ahi = am; bhi = bm;
            }
            float cf = (float)lane;
            int   ci = lane;
            #pragma unroll 2
            for (int j = 0; j < STEPS_PER_LANE; ++j, cf += 32.0f, ci += 32) {
                const float rlo = fmaxf(fmaf(cf, blo, alo) - 0.01f, 0.0f);
                const float rhi = fminf(fmaf(cf, bhi, ahi) + 0.01f, (float)(R_-1));
                const int ir0 = __float2int_ru(rlo);
                const int n   = __float2int_rd(rhi) - ir0;
                if (n >= 0) {
                    const float rf0 = (float)ir0;
                    const float Qp0 = fmaf(rf0, qr, fmaf(cf, qc, q0));
                    const float Bp0 = fmaf(rf0, br, fmaf(cf, bc, b0));
                    const float* p  = img + ir0*C_ + ci;
                    #pragma unroll
                    for (int k = 0; k < 4; ++k) {
                        if (k <= n) {
                            const float Qp = fmaf((float)k, qr, Qp0);
                            const float Bp = fmaf((float)k, br, Bp0);
                            const float w  = 1.0f - __fdividef(fabsf(Qp), Bp);
                            if (w > 0.0f)
                                acc = fmaf(w, __ldg(p + k*C_), acc);
                        }
                    }
                    for (int k = 4; k <= n; ++k) {     // rare tail
                        const float Qp = fmaf((float)k, qr, Qp0);
                        const float Bp = fmaf((float)k, br, Bp0);
                        const float w  = 1.0f - __fdividef(fabsf(Qp), Bp);
                        if (w > 0.0f)
                            acc = fmaf(w, __ldg(p + k*C_), acc);
                    }
                }
            }
        } else {
            // ---- drive over r (lanes take r = lane + 32k); solve c range ----
            const float gm = qc + bc, gp = qc - bc;
            const float invm = 1.0f/gm, invp = 1.0f/gp;
            float am = -(q0 + b0)*invm, bm = -(qr + br)*invm;
            float ap = -(q0 - b0)*invp, bp2 = -(qr - br)*invp;
            float alo, blo, ahi, bhi;
            if (fmaf(191.5f, bm, am) <= fmaf(191.5f, bp2, ap)) {
                alo = am; blo = bm; ahi = ap; bhi = bp2;
            } else {
                alo = ap; blo = bp2; ahi = am; bhi = bm;
            }
            float rfd = (float)lane;
            int   ri  = lane;
            #pragma unroll 2
            for (int j = 0; j < STEPS_PER_LANE; ++j, rfd += 32.0f, ri += 32) {
                const float clo = fmaxf(fmaf(rfd, blo, alo) - 0.01f, 0.0f);
                const float chi = fminf(fmaf(rfd, bhi, ahi) + 0.01f, (float)(C_-1));
                const int ic0 = __float2int_ru(clo);
                const int n   = __float2int_rd(chi) - ic0;
                if (n >= 0) {
                    const float cf0 = (float)ic0;
                    const float Qp0 = fmaf(cf0, qc, fmaf(rfd, qr, q0));
                    const float Bp0 = fmaf(cf0, bc, fmaf(rfd, br, b0));
                    const float* p  = img + ri*C_ + ic0;
                    #pragma unroll
                    for (int k = 0; k < 4; ++k) {
                        if (k <= n) {
                            const float Qp = fmaf((float)k, qc, Qp0);
                            const float Bp = fmaf((float)k, bc, Bp0);
                            const float w  = 1.0f - __fdividef(fabsf(Qp), Bp);
                            if (w > 0.0f)
                                acc = fmaf(w, __ldg(p + k), acc);
                        }
                    }
                    for (int k = 4; k <= n; ++k) {     // rare tail
                        const float Qp = fmaf((float)k, qc, Qp0);
                        const float Bp = fmaf((float)k, bc, Bp0);
                        const float w  = 1.0f - __fdividef(fabsf(Qp), Bp);
                        if (w > 0.0f)
                            acc = fmaf(w, __ldg(p + k), acc);
                    }
                }
            }
        }
    }

    #pragma unroll
    for (int off = 16; off > 0; off >>= 1)
        acc += __shfl_xor_sync(0xffffffffu, acc, off);

    if (lane == 0)
        sino[v*NCOLS_ + i] = acc;
}

extern "C" void kernel_launch(void* const* d_in, const int* in_sizes, int n_in,
                              void* d_out, int out_size)
{
    const float* img    = (const float*)d_in[0];
    const float* src    = (const float*)d_in[1];
    const float* detc   = (const float*)d_in[2];
    const float* u      = (const float*)d_in[3];
    const float* center = (const float*)d_in[4];
    const float* cdir   = (const float*)d_in[5];
    float* sino = (float*)d_out;

    dim3 grid(NCOLS_ / WARPS_PER_BLOCK, V_);
    dim3 block(32 * WARPS_PER_BLOCK);
    fanbeam_fp_kernel<<<grid, block>>>(img, src, detc, u, center, cdir, sino);
}

// round 6
// speedup vs baseline: 5.7202x; 1.0821x over previous
#include <cuda_runtime.h>

// Fan-beam CT forward projector — warp-cooperative gather,
// driving-window clipping + slim (unroll-2) inner loop.
constexpr int   R_      = 384;
constexpr int   C_      = 384;
constexpr int   NCOLS_  = 768;
constexpr int   V_      = 256;
constexpr float DR_     = 1.0f;
constexpr float DC_     = 1.0f;
constexpr float DSPACE_ = 1.5f;

constexpr int WARPS_PER_BLOCK = 4;

struct VG {
    float K, A;
    float bn0, dnr, dnc;
    float bu0, dur, duc;
    float dzx, dzy, sx, sy;
    float ux, uy, rowx, rowy, colx, coly;
};

// window for: (ahi + bhi*c >= -0.01) && (alo + blo*c <= lim + 0.01), c in [0, cmax]
// returns superset interval [w0, w1] (empty if w0 > w1)
__device__ __forceinline__ void drive_window(float ahi, float bhi,
                                             float alo, float blo,
                                             float lim, float cmax,
                                             int& w0, int& w1)
{
    float f0 = 0.0f, f1 = cmax;
    const float eps = 1e-12f;
    // hi-line >= -0.01
    if (bhi > eps)        f0 = fmaxf(f0, __fdividef(-0.01f - ahi, bhi) - 1.0f);
    else if (bhi < -eps)  f1 = fminf(f1, __fdividef(-0.01f - ahi, bhi) + 1.0f);
    else if (ahi < -0.01f) { w0 = 1; w1 = 0; return; }
    // lo-line <= lim + 0.01
    const float L = lim + 0.01f;
    if (blo > eps)        f1 = fminf(f1, __fdividef(L - alo, blo) + 1.0f);
    else if (blo < -eps)  f0 = fmaxf(f0, __fdividef(L - alo, blo) - 1.0f);
    else if (alo > L)     { w0 = 1; w1 = 0; return; }
    w0 = max(0, __float2int_ru(f0));
    w1 = min((int)cmax, __float2int_rd(f1));
}

__global__ __launch_bounds__(32 * WARPS_PER_BLOCK)
void fanbeam_fp_kernel(const float* __restrict__ img,
                       const float* __restrict__ src_g,
                       const float* __restrict__ detc_g,
                       const float* __restrict__ u_g,
                       const float* __restrict__ center_g,
                       const float* __restrict__ cdir_g,
                       float* __restrict__ sino)
{
    const int v    = blockIdx.y;
    const int warp = threadIdx.x >> 5;
    const int lane = threadIdx.x & 31;
    const int i    = blockIdx.x * WARPS_PER_BLOCK + warp;

    __shared__ VG g;
    if (threadIdx.x == 0) {
        const float sx  = src_g [2*v+0], sy  = src_g [2*v+1];
        const float dcx = detc_g[2*v+0], dcy = detc_g[2*v+1];
        const float ux  = u_g  [2*v+0], uy  = u_g  [2*v+1];
        const float nx  = -uy,          ny  = ux;
        const float cx  = center_g[0],  cy  = center_g[1];
        const float colx = cdir_g[0],   coly = cdir_g[1];
        const float rowx = -coly,       rowy = colx;

        const float vzx = cx - 0.5f*(R_-1)*DR_*rowx - 0.5f*(C_-1)*DC_*colx;
        const float vzy = cy - 0.5f*(R_-1)*DR_*rowy - 0.5f*(C_-1)*DC_*coly;

        const float src_d = sx*nx + sy*ny;
        const float su    = sx*ux + sy*uy;
        const float K     = (dcx*nx + dcy*ny) - src_d;
        const float h     = 0.5f*(NCOLS_-1)*DSPACE_;
        const float dzx   = dcx - h*ux, dzy = dcy - h*uy;
        const float A     = su - (dzx*ux + dzy*uy);

        g.K = K; g.A = A;
        g.bn0 = vzx*nx + vzy*ny - src_d;
        g.dnr = DR_*(rowx*nx + rowy*ny);
        g.dnc = DC_*(colx*nx + coly*ny);
        g.bu0 = vzx*ux + vzy*uy - su;
        g.dur = DR_*(rowx*ux + rowy*uy);
        g.duc = DC_*(colx*ux + coly*uy);
        g.dzx = dzx; g.dzy = dzy; g.sx = sx; g.sy = sy;
        g.ux = ux; g.uy = uy;
        g.rowx = rowx; g.rowy = rowy; g.colx = colx; g.coly = coly;
    }
    __syncthreads();

    const float K = g.K, A = g.A;
    const float bn0 = g.bn0, dnr = g.dnr, dnc = g.dnc;
    const float bu0 = g.bu0, dur = g.dur, duc = g.duc;

    const float den_c = bn0 + 0.5f*(R_-1)*dnr + 0.5f*(C_-1)*dnc;
    const float sig   = (den_c > 0.0f) ? 1.0f : -1.0f;
    const bool  tok   = (sig * K) > 0.0f;

    const float E  = A - (float)i * DSPACE_;
    const float q0 = sig * (E*bn0 + K*bu0);
    const float qr = sig * (E*dnr + K*dur);
    const float qc = sig * (E*dnc + K*duc);
    const float b0 = sig * DSPACE_ * bn0;
    const float br = sig * DSPACE_ * dnr;
    const float bc = sig * DSPACE_ * dnc;

    const float bxp = g.dzx + (float)i*DSPACE_*g.ux - g.sx;
    const float byp = g.dzy + (float)i*DSPACE_*g.uy - g.sy;
    const float dc_comp = bxp*g.colx + byp*g.coly;
    const float dr_comp = bxp*g.rowx + byp*g.rowy;

    float acc = 0.0f;

    if (tok) {
        if (fabsf(dc_comp) >= fabsf(dr_comp)) {
            // ---- drive over c; solve r range ----
            const float gm = qr + br, gp = qr - br;
            const float invm = 1.0f/gm, invp = 1.0f/gp;
            const float am = -(q0 + b0)*invm, bm = -(qc + bc)*invm;
            const float ap = -(q0 - b0)*invp, bp2 = -(qc - bc)*invp;
            float alo, blo, ahi, bhi;
            if (fmaf(191.5f, bm, am) <= fmaf(191.5f, bp2, ap)) {
                alo = am; blo = bm; ahi = ap; bhi = bp2;
            } else {
                alo = ap; blo = bp2; ahi = am; bhi = bm;
            }
            int w0, w1;
            drive_window(ahi, bhi, alo, blo, (float)(R_-1), (float)(C_-1), w0, w1);
            for (int ci = w0 + lane; ci <= w1; ci += 32) {
                const float cf  = (float)ci;
                const float rlo = fmaxf(fmaf(cf, blo, alo) - 0.01f, 0.0f);
                const float rhi = fminf(fmaf(cf, bhi, ahi) + 0.01f, (float)(R_-1));
                const int ir0 = __float2int_ru(rlo);
                const int n   = __float2int_rd(rhi) - ir0;
                if (n >= 0) {
                    const float rf0 = (float)ir0;
                    const float Qp0 = fmaf(rf0, qr, fmaf(cf, qc, q0));
                    const float Bp0 = fmaf(rf0, br, fmaf(cf, bc, b0));
                    const float* p  = img + ir0*C_ + ci;
                    {   // k = 0
                        const float w = 1.0f - __fdividef(fabsf(Qp0), Bp0);
                        if (w > 0.0f) acc = fmaf(w, __ldg(p), acc);
                    }
                    if (n >= 1) {   // k = 1
                        const float Qp = Qp0 + qr, Bp = Bp0 + br;
                        const float w  = 1.0f - __fdividef(fabsf(Qp), Bp);
                        if (w > 0.0f) acc = fmaf(w, __ldg(p + C_), acc);
                    }
                    for (int k = 2; k <= n; ++k) {   // rare tail
                        const float Qp = fmaf((float)k, qr, Qp0);
                        const float Bp = fmaf((float)k, br, Bp0);
                        const float w  = 1.0f - __fdividef(fabsf(Qp), Bp);
                        if (w > 0.0f) acc = fmaf(w, __ldg(p + k*C_), acc);
                    }
                }
            }
        } else {
            // ---- drive over r; solve c range ----
            const float gm = qc + bc, gp = qc - bc;
            const float invm = 1.0f/gm, invp = 1.0f/gp;
            const float am = -(q0 + b0)*invm, bm = -(qr + br)*invm;
            const float ap = -(q0 - b0)*invp, bp2 = -(qr - br)*invp;
            float alo, blo, ahi, bhi;
            if (fmaf(191.5f, bm, am) <= fmaf(191.5f, bp2, ap)) {
                alo = am; blo = bm; ahi = ap; bhi = bp2;
            } else {
                alo = ap; blo = bp2; ahi = am; bhi = bm;
            }
            int w0, w1;
            drive_window(ahi, bhi, alo, blo, (float)(C_-1), (float)(R_-1), w0, w1);
            for (int ri = w0 + lane; ri <= w1; ri += 32) {
                const float rfd = (float)ri;
                const float clo = fmaxf(fmaf(rfd, blo, alo) - 0.01f, 0.0f);
                const float chi = fminf(fmaf(rfd, bhi, ahi) + 0.01f, (float)(C_-1));
                const int ic0 = __float2int_ru(clo);
                const int n   = __float2int_rd(chi) - ic0;
                if (n >= 0) {
                    const float cf0 = (float)ic0;
                    const float Qp0 = fmaf(cf0, qc, fmaf(rfd, qr, q0));
                    const float Bp0 = fmaf(cf0, bc, fmaf(rfd, br, b0));
                    const float* p  = img + ri*C_ + ic0;
                    {   // k = 0
                        const float w = 1.0f - __fdividef(fabsf(Qp0), Bp0);
                        if (w > 0.0f) acc = fmaf(w, __ldg(p), acc);
                    }
                    if (n >= 1) {   // k = 1
                        const float Qp = Qp0 + qc, Bp = Bp0 + bc;
                        const float w  = 1.0f - __fdividef(fabsf(Qp), Bp);
                        if (w > 0.0f) acc = fmaf(w, __ldg(p + 1), acc);
                    }
                    for (int k = 2; k <= n; ++k) {   // rare tail
                        const float Qp = fmaf((float)k, qc, Qp0);
                        const float Bp = fmaf((float)k, bc, Bp0);
                        const float w  = 1.0f - __fdividef(fabsf(Qp), Bp);
                        if (w > 0.0f) acc = fmaf(w, __ldg(p + k), acc);
                    }
                }
            }
        }
    }

    #pragma unroll
    for (int off = 16; off > 0; off >>= 1)
        acc += __shfl_xor_sync(0xffffffffu, acc, off);

    if (lane == 0)
        sino[v*NCOLS_ + i] = acc;
}

extern "C" void kernel_launch(void* const* d_in, const int* in_sizes, int n_in,
                              void* d_out, int out_size)
{
    const float* img    = (const float*)d_in[0];
    const float* src    = (const float*)d_in[1];
    const float* detc   = (const float*)d_in[2];
    const float* u      = (const float*)d_in[3];
    const float* center = (const float*)d_in[4];
    const float* cdir   = (const float*)d_in[5];
    float* sino = (float*)d_out;

    dim3 grid(NCOLS_ / WARPS_PER_BLOCK, V_);
    dim3 block(32 * WARPS_PER_BLOCK);
    fanbeam_fp_kernel<<<grid, block>>>(img, src, detc, u, center, cdir, sino);
}

// round 7
// speedup vs baseline: 7.1599x; 1.2517x over previous
#include <cuda_runtime.h>

// Fan-beam CT forward projector — warp-cooperative gather over BIN PAIRS.
// Q_{i+1} = Q_i - B  => one pixel visit feeds two detector bins.
constexpr int   R_      = 384;
constexpr int   C_      = 384;
constexpr int   NCOLS_  = 768;
constexpr int   V_      = 256;
constexpr float DR_     = 1.0f;
constexpr float DC_     = 1.0f;
constexpr float DSPACE_ = 1.5f;

constexpr int WARPS_PER_BLOCK = 4;
constexpr int NPAIRS = NCOLS_ / 2;     // 384

struct VG {
    float K, A;
    float bn0, dnr, dnc;
    float bu0, dur, duc;
    float dzx, dzy, sx, sy;
    float ux, uy, rowx, rowy, colx, coly;
};

// window for: (ahi + bhi*s >= -0.01) && (alo + blo*s <= lim + 0.01), s in [0, smax]
__device__ __forceinline__ void drive_window(float ahi, float bhi,
                                             float alo, float blo,
                                             float lim, float smax,
                                             int& w0, int& w1)
{
    float f0 = 0.0f, f1 = smax;
    const float eps = 1e-12f;
    if (bhi > eps)        f0 = fmaxf(f0, __fdividef(-0.01f - ahi, bhi) - 1.0f);
    else if (bhi < -eps)  f1 = fminf(f1, __fdividef(-0.01f - ahi, bhi) + 1.0f);
    else if (ahi < -0.01f) { w0 = 1; w1 = 0; return; }
    const float L = lim + 0.01f;
    if (blo > eps)        f1 = fminf(f1, __fdividef(L - alo, blo) + 1.0f);
    else if (blo < -eps)  f0 = fmaxf(f0, __fdividef(L - alo, blo) - 1.0f);
    else if (alo > L)     { w0 = 1; w1 = 0; return; }
    w0 = max(0, __float2int_ru(f0));
    w1 = min((int)smax, __float2int_rd(f1));
}

__global__ __launch_bounds__(32 * WARPS_PER_BLOCK)
void fanbeam_fp_kernel(const float* __restrict__ img,
                       const float* __restrict__ src_g,
                       const float* __restrict__ detc_g,
                       const float* __restrict__ u_g,
                       const float* __restrict__ center_g,
                       const float* __restrict__ cdir_g,
                       float* __restrict__ sino)
{
    const int v    = blockIdx.y;
    const int warp = threadIdx.x >> 5;
    const int lane = threadIdx.x & 31;
    const int pair = blockIdx.x * WARPS_PER_BLOCK + warp;   // 0..383
    const int ib   = pair * 2;                              // base bin

    __shared__ VG g;
    if (threadIdx.x == 0) {
        const float sx  = src_g [2*v+0], sy  = src_g [2*v+1];
        const float dcx = detc_g[2*v+0], dcy = detc_g[2*v+1];
        const float ux  = u_g  [2*v+0], uy  = u_g  [2*v+1];
        const float nx  = -uy,          ny  = ux;
        const float cx  = center_g[0],  cy  = center_g[1];
        const float colx = cdir_g[0],   coly = cdir_g[1];
        const float rowx = -coly,       rowy = colx;

        const float vzx = cx - 0.5f*(R_-1)*DR_*rowx - 0.5f*(C_-1)*DC_*colx;
        const float vzy = cy - 0.5f*(R_-1)*DR_*rowy - 0.5f*(C_-1)*DC_*coly;

        const float src_d = sx*nx + sy*ny;
        const float su    = sx*ux + sy*uy;
        const float K     = (dcx*nx + dcy*ny) - src_d;
        const float h     = 0.5f*(NCOLS_-1)*DSPACE_;
        const float dzx   = dcx - h*ux, dzy = dcy - h*uy;
        const float A     = su - (dzx*ux + dzy*uy);

        g.K = K; g.A = A;
        g.bn0 = vzx*nx + vzy*ny - src_d;
        g.dnr = DR_*(rowx*nx + rowy*ny);
        g.dnc = DC_*(colx*nx + coly*ny);
        g.bu0 = vzx*ux + vzy*uy - su;
        g.dur = DR_*(rowx*ux + rowy*uy);
        g.duc = DC_*(colx*ux + coly*uy);
        g.dzx = dzx; g.dzy = dzy; g.sx = sx; g.sy = sy;
        g.ux = ux; g.uy = uy;
        g.rowx = rowx; g.rowy = rowy; g.colx = colx; g.coly = coly;
    }
    __syncthreads();

    const float K = g.K, A = g.A;
    const float bn0 = g.bn0, dnr = g.dnr, dnc = g.dnc;
    const float bu0 = g.bu0, dur = g.dur, duc = g.duc;

    const float den_c = bn0 + 0.5f*(R_-1)*dnr + 0.5f*(C_-1)*dnc;
    const float sig   = (den_c > 0.0f) ? 1.0f : -1.0f;
    const bool  tok   = (sig * K) > 0.0f;

    // Q for bin ib; B = sig*DS*den. Q/B = col - ib.
    const float E  = A - (float)ib * DSPACE_;
    const float q0 = sig * (E*bn0 + K*bu0);
    const float qr = sig * (E*dnr + K*dur);
    const float qc = sig * (E*dnc + K*duc);
    const float b0 = sig * DSPACE_ * bn0;
    const float br = sig * DSPACE_ * dnr;
    const float bc = sig * DSPACE_ * dnc;

    // axis choice from pair-central ray
    const float ic_f = (float)ib + 0.5f;
    const float bxp = g.dzx + ic_f*DSPACE_*g.ux - g.sx;
    const float byp = g.dzy + ic_f*DSPACE_*g.uy - g.sy;
    const float dc_comp = bxp*g.colx + byp*g.coly;
    const float dr_comp = bxp*g.rowx + byp*g.rowy;

    float acc0 = 0.0f, acc1 = 0.0f;

    if (tok) {
        const bool drive_c = fabsf(dc_comp) >= fabsf(dr_comp);
        // select per-axis linear coefficients (driving coord s, perp coord p)
        //   Q = q0 + s*qs + p*qp ; B = b0 + s*bs + p*bp
        const float qs = drive_c ? qc : qr;
        const float qp = drive_c ? qr : qc;
        const float bs = drive_c ? bc : br;
        const float bp = drive_c ? br : bc;
        const float plim = 383.0f;                 // R_-1 == C_-1
        // wedge lines: Lm: Q + B = 0 (col = ib-1) ; Lp: Q - 2B = 0 (col = ib+2)
        const float gm = qp + bs*0.0f + bp;        // d(Q+B)/dp
        const float gp2 = qp - 2.0f*bp;            // d(Q-2B)/dp
        const float am = __fdividef(-(q0 + b0),  gm);
        const float bm = __fdividef(-(qs + bs),  gm);
        const float ap = __fdividef(-(q0 - 2.0f*b0), gp2);
        const float bp3 = __fdividef(-(qs - 2.0f*bs), gp2);
        // constant boundary ordering (lines cross at source, outside image)
        float alo, blo, ahi, bhi;
        if (fmaf(191.5f, bm, am) <= fmaf(191.5f, bp3, ap)) {
            alo = am; blo = bm; ahi = ap; bhi = bp3;
        } else {
            alo = ap; blo = bp3; ahi = am; bhi = bm;
        }
        int w0i, w1i;
        drive_window(ahi, bhi, alo, blo, plim, 383.0f, w0i, w1i);

        const int pstride = drive_c ? C_ : 1;      // step in perp direction
        for (int s = w0i + lane; s <= w1i; s += 32) {
            const float sf  = (float)s;
            const float plo = fmaxf(fmaf(sf, blo, alo) - 0.01f, 0.0f);
            const float phi = fminf(fmaf(sf, bhi, ahi) + 0.01f, plim);
            const int p0 = __float2int_ru(plo);
            const int n  = __float2int_rd(phi) - p0;
            if (n >= 0) {
                const float pf0 = (float)p0;
                const float Qb = fmaf(pf0, qp, fmaf(sf, qs, q0));
                const float Bb = fmaf(pf0, bp, fmaf(sf, bs, b0));
                const float* ptr = drive_c ? (img + p0*C_ + s)
                                           : (img + s*C_ + p0);
                #pragma unroll
                for (int k = 0; k < 4; ++k) {
                    if (k <= n) {
                        const float Qp = fmaf((float)k, qp, Qb);
                        const float Bp = fmaf((float)k, bp, Bb);
                        const float rb = __fdividef(1.0f, Bp);
                        const float val = __ldg(ptr + k*pstride);
                        const float wA = fmaf(-fabsf(Qp), rb, 1.0f);
                        const float wB = fmaf(-fabsf(Qp - Bp), rb, 1.0f);
                        acc0 = fmaf(fmaxf(wA, 0.0f), val, acc0);
                        acc1 = fmaf(fmaxf(wB, 0.0f), val, acc1);
                    }
                }
                for (int k = 4; k <= n; ++k) {      // rare tail
                    const float Qp = fmaf((float)k, qp, Qb);
                    const float Bp = fmaf((float)k, bp, Bb);
                    const float rb = __fdividef(1.0f, Bp);
                    const float val = __ldg(ptr + k*pstride);
                    const float wA = fmaf(-fabsf(Qp), rb, 1.0f);
                    const float wB = fmaf(-fabsf(Qp - Bp), rb, 1.0f);
                    acc0 = fmaf(fmaxf(wA, 0.0f), val, acc0);
                    acc1 = fmaf(fmaxf(wB, 0.0f), val, acc1);
                }
            }
        }
    }

    #pragma unroll
    for (int off = 16; off > 0; off >>= 1) {
        acc0 += __shfl_xor_sync(0xffffffffu, acc0, off);
        acc1 += __shfl_xor_sync(0xffffffffu, acc1, off);
    }

    if (lane == 0) {
        sino[v*NCOLS_ + ib]     = acc0;
        sino[v*NCOLS_ + ib + 1] = acc1;
    }
}

extern "C" void kernel_launch(void* const* d_in, const int* in_sizes, int n_in,
                              void* d_out, int out_size)
{
    const float* img    = (const float*)d_in[0];
    const float* src    = (const float*)d_in[1];
    const float* detc   = (const float*)d_in[2];
    const float* u      = (const float*)d_in[3];
    const float* center = (const float*)d_in[4];
    const float* cdir   = (const float*)d_in[5];
    float* sino = (float*)d_out;

    dim3 grid(NPAIRS / WARPS_PER_BLOCK, V_);
    dim3 block(32 * WARPS_PER_BLOCK);
    fanbeam_fp_kernel<<<grid, block>>>(img, src, detc, u, center, cdir, sino);
}

// round 8
// speedup vs baseline: 7.2168x; 1.0079x over previous
#include <cuda_runtime.h>

// Fan-beam CT forward projector — warp-cooperative gather over BIN PAIRS,
// axis-split templated inner loop (compile-time perp stride), unroll-5.
constexpr int   R_      = 384;
constexpr int   C_      = 384;
constexpr int   NCOLS_  = 768;
constexpr int   V_      = 256;
constexpr float DR_     = 1.0f;
constexpr float DC_     = 1.0f;
constexpr float DSPACE_ = 1.5f;

constexpr int WARPS_PER_BLOCK = 4;
constexpr int NPAIRS = NCOLS_ / 2;     // 384

struct VG {
    float K, A;
    float bn0, dnr, dnc;
    float bu0, dur, duc;
    float dzx, dzy, sx, sy;
    float ux, uy, rowx, rowy, colx, coly;
};

__device__ __forceinline__ void drive_window(float ahi, float bhi,
                                             float alo, float blo,
                                             float lim, float smax,
                                             int& w0, int& w1)
{
    float f0 = 0.0f, f1 = smax;
    const float eps = 1e-12f;
    if (bhi > eps)        f0 = fmaxf(f0, __fdividef(-0.01f - ahi, bhi) - 1.0f);
    else if (bhi < -eps)  f1 = fminf(f1, __fdividef(-0.01f - ahi, bhi) + 1.0f);
    else if (ahi < -0.01f) { w0 = 1; w1 = 0; return; }
    const float L = lim + 0.01f;
    if (blo > eps)        f1 = fminf(f1, __fdividef(L - alo, blo) + 1.0f);
    else if (blo < -eps)  f0 = fmaxf(f0, __fdividef(L - alo, blo) - 1.0f);
    else if (alo > L)     { w0 = 1; w1 = 0; return; }
    w0 = max(0, __float2int_ru(f0));
    w1 = min((int)smax, __float2int_rd(f1));
}

// Walk driving coordinate s (lanes strided by 32), perp coord p with
// compile-time stride PSTR (384 => perp is row, 1 => perp is col).
// SROW: element stride of s in the image (the complementary one).
template<int PSTR, int SROW>
__device__ __forceinline__ void walk(const float* __restrict__ img,
                                     int lane,
                                     float q0, float qs, float qp,
                                     float b0, float bs, float bp,
                                     float alo, float blo, float ahi, float bhi,
                                     float& acc0, float& acc1)
{
    int w0i, w1i;
    drive_window(ahi, bhi, alo, blo, 383.0f, 383.0f, w0i, w1i);

    for (int s = w0i + lane; s <= w1i; s += 32) {
        const float sf  = (float)s;
        const float plo = fmaxf(fmaf(sf, blo, alo) - 0.01f, 0.0f);
        const float phi = fminf(fmaf(sf, bhi, ahi) + 0.01f, 383.0f);
        const int p0 = __float2int_ru(plo);
        const int n  = __float2int_rd(phi) - p0;
        if (n >= 0) {
            const float pf0 = (float)p0;
            const float Qb  = fmaf(pf0, qp, fmaf(sf, qs, q0));
            const float Bb  = fmaf(pf0, bp, fmaf(sf, bs, b0));
            const float* p  = img + p0*PSTR + s*SROW;
            #pragma unroll
            for (int k = 0; k < 5; ++k) {
                if (k <= n) {
                    const float Qp = fmaf((float)k, qp, Qb);
                    const float Bp = fmaf((float)k, bp, Bb);
                    const float rb = __fdividef(1.0f, Bp);
                    const float val = __ldg(p + k*PSTR);
                    const float wA = fmaf(-fabsf(Qp), rb, 1.0f);
                    const float wB = fmaf(-fabsf(Qp - Bp), rb, 1.0f);
                    acc0 = fmaf(fmaxf(wA, 0.0f), val, acc0);
                    acc1 = fmaf(fmaxf(wB, 0.0f), val, acc1);
                }
            }
            for (int k = 5; k <= n; ++k) {          // rare tail
                const float Qp = fmaf((float)k, qp, Qb);
                const float Bp = fmaf((float)k, bp, Bb);
                const float rb = __fdividef(1.0f, Bp);
                const float val = __ldg(p + k*PSTR);
                const float wA = fmaf(-fabsf(Qp), rb, 1.0f);
                const float wB = fmaf(-fabsf(Qp - Bp), rb, 1.0f);
                acc0 = fmaf(fmaxf(wA, 0.0f), val, acc0);
                acc1 = fmaf(fmaxf(wB, 0.0f), val, acc1);
            }
        }
    }
}

__global__ __launch_bounds__(32 * WARPS_PER_BLOCK)
void fanbeam_fp_kernel(const float* __restrict__ img,
                       const float* __restrict__ src_g,
                       const float* __restrict__ detc_g,
                       const float* __restrict__ u_g,
                       const float* __restrict__ center_g,
                       const float* __restrict__ cdir_g,
                       float* __restrict__ sino)
{
    const int v    = blockIdx.y;
    const int warp = threadIdx.x >> 5;
    const int lane = threadIdx.x & 31;
    const int pair = blockIdx.x * WARPS_PER_BLOCK + warp;   // 0..383
    const int ib   = pair * 2;

    __shared__ VG g;
    if (threadIdx.x == 0) {
        const float sx  = src_g [2*v+0], sy  = src_g [2*v+1];
        const float dcx = detc_g[2*v+0], dcy = detc_g[2*v+1];
        const float ux  = u_g  [2*v+0], uy  = u_g  [2*v+1];
        const float nx  = -uy,          ny  = ux;
        const float cx  = center_g[0],  cy  = center_g[1];
        const float colx = cdir_g[0],   coly = cdir_g[1];
        const float rowx = -coly,       rowy = colx;

        const float vzx = cx - 0.5f*(R_-1)*DR_*rowx - 0.5f*(C_-1)*DC_*colx;
        const float vzy = cy - 0.5f*(R_-1)*DR_*rowy - 0.5f*(C_-1)*DC_*coly;

        const float src_d = sx*nx + sy*ny;
        const float su    = sx*ux + sy*uy;
        const float K     = (dcx*nx + dcy*ny) - src_d;
        const float h     = 0.5f*(NCOLS_-1)*DSPACE_;
        const float dzx   = dcx - h*ux, dzy = dcy - h*uy;
        const float A     = su - (dzx*ux + dzy*uy);

        g.K = K; g.A = A;
        g.bn0 = vzx*nx + vzy*ny - src_d;
        g.dnr = DR_*(rowx*nx + rowy*ny);
        g.dnc = DC_*(colx*nx + coly*ny);
        g.bu0 = vzx*ux + vzy*uy - su;
        g.dur = DR_*(rowx*ux + rowy*uy);
        g.duc = DC_*(colx*ux + coly*uy);
        g.dzx = dzx; g.dzy = dzy; g.sx = sx; g.sy = sy;
        g.ux = ux; g.uy = uy;
        g.rowx = rowx; g.rowy = rowy; g.colx = colx; g.coly = coly;
    }
    __syncthreads();

    const float K = g.K, A = g.A;
    const float bn0 = g.bn0, dnr = g.dnr, dnc = g.dnc;
    const float bu0 = g.bu0, dur = g.dur, duc = g.duc;

    const float den_c = bn0 + 0.5f*(R_-1)*dnr + 0.5f*(C_-1)*dnc;
    const float sig   = (den_c > 0.0f) ? 1.0f : -1.0f;
    const bool  tok   = (sig * K) > 0.0f;

    // Q for bin ib; B = sig*DS*den. Q/B = col - ib.
    const float E  = A - (float)ib * DSPACE_;
    const float q0 = sig * (E*bn0 + K*bu0);
    const float qr = sig * (E*dnr + K*dur);
    const float qc = sig * (E*dnc + K*duc);
    const float b0 = sig * DSPACE_ * bn0;
    const float br = sig * DSPACE_ * dnr;
    const float bc = sig * DSPACE_ * dnc;

    const float ic_f = (float)ib + 0.5f;
    const float bxp = g.dzx + ic_f*DSPACE_*g.ux - g.sx;
    const float byp = g.dzy + ic_f*DSPACE_*g.uy - g.sy;
    const float dc_comp = bxp*g.colx + byp*g.coly;
    const float dr_comp = bxp*g.rowx + byp*g.rowy;

    float acc0 = 0.0f, acc1 = 0.0f;

    if (tok) {
        const bool drive_c = fabsf(dc_comp) >= fabsf(dr_comp);
        // pair wedge lines: Q + B = 0 (col = ib-1) and Q - 2B = 0 (col = ib+2)
        const float qs = drive_c ? qc : qr;
        const float qp = drive_c ? qr : qc;
        const float bs = drive_c ? bc : br;
        const float bp = drive_c ? br : bc;
        const float gm  = qp + bp;
        const float gp2 = qp - 2.0f*bp;
        const float am  = __fdividef(-(q0 + b0),       gm);
        const float bm  = __fdividef(-(qs + bs),       gm);
        const float ap  = __fdividef(-(q0 - 2.0f*b0),  gp2);
        const float bp3 = __fdividef(-(qs - 2.0f*bs),  gp2);
        float alo, blo, ahi, bhi;
        if (fmaf(191.5f, bm, am) <= fmaf(191.5f, bp3, ap)) {
            alo = am; blo = bm; ahi = ap; bhi = bp3;
        } else {
            alo = ap; blo = bp3; ahi = am; bhi = bm;
        }
        if (drive_c)
            walk<C_, 1>(img, lane, q0, qs, qp, b0, bs, bp,
                        alo, blo, ahi, bhi, acc0, acc1);
        else
            walk<1, C_>(img, lane, q0, qs, qp, b0, bs, bp,
                        alo, blo, ahi, bhi, acc0, acc1);
    }

    #pragma unroll
    for (int off = 16; off > 0; off >>= 1) {
        acc0 += __shfl_xor_sync(0xffffffffu, acc0, off);
        acc1 += __shfl_xor_sync(0xffffffffu, acc1, off);
    }

    if (lane == 0) {
        sino[v*NCOLS_ + ib]     = acc0;
        sino[v*NCOLS_ + ib + 1] = acc1;
    }
}

extern "C" void kernel_launch(void* const* d_in, const int* in_sizes, int n_in,
                              void* d_out, int out_size)
{
    const float* img    = (const float*)d_in[0];
    const float* src    = (const float*)d_in[1];
    const float* detc   = (const float*)d_in[2];
    const float* u      = (const float*)d_in[3];
    const float* center = (const float*)d_in[4];
    const float* cdir   = (const float*)d_in[5];
    float* sino = (float*)d_out;

    dim3 grid(NPAIRS / WARPS_PER_BLOCK, V_);
    dim3 block(32 * WARPS_PER_BLOCK);
    fanbeam_fp_kernel<<<grid, block>>>(img, src, detc, u, center, cdir, sino);
}